// round 14
// baseline (speedup 1.0000x reference)
#include <cuda_runtime.h>
#include <cuda_fp16.h>
#include <cstdint>

#define BB 2
#define TT 2048
#define DM 1024
#define NH 16
#define DH 64
#define MM (BB * TT)   // 4096

// Scratch (device globals; no allocation allowed)
__device__ uint32_t g_q[BB * NH * TT * (DH / 2)];   // fp16 [B,H,T,Dh], *0.125*log2e
__device__ uint32_t g_k[BB * NH * TT * (DH / 2)];   // fp16 [B,H,T,Dh]
__device__ uint16_t g_vt[BB * NH * DH * TT];        // fp16 [B,H,Dh,T] (transposed)
__device__ uint32_t g_attp[MM * DM / 2];            // attn out, fp16 packed-A frags
__device__ uint32_t g_xp[MM * DM / 2];              // x fp16 packed-A frags
__device__ uint32_t g_wp[4 * DM * DM / 2];          // W's fp16 packed-B frags

// ---------------------------------------------------------------------------
// helpers
// ---------------------------------------------------------------------------
__device__ __forceinline__ uint32_t smem_u32(const void* p) {
  uint32_t a;
  asm("{ .reg .u64 t; cvta.to.shared.u64 t, %1; cvt.u32.u64 %0, t; }"
      : "=r"(a) : "l"(p));
  return a;
}

__device__ __forceinline__ uint32_t h2u(float lo, float hi) {
  __half2 h = __floats2half2_rn(lo, hi);
  return *reinterpret_cast<uint32_t*>(&h);
}

// fp16 m16n8k16
__device__ __forceinline__ void mma16(float* c, const unsigned* a,
                                      unsigned b0, unsigned b1) {
  asm("mma.sync.aligned.m16n8k16.row.col.f32.f16.f16.f32 "
      "{%0,%1,%2,%3},{%4,%5,%6,%7},{%8,%9},{%0,%1,%2,%3};"
      : "+f"(c[0]), "+f"(c[1]), "+f"(c[2]), "+f"(c[3])
      : "r"(a[0]), "r"(a[1]), "r"(a[2]), "r"(a[3]), "r"(b0), "r"(b1));
}

#define CP_ASYNC16(dst, src) \
  asm volatile("cp.async.cg.shared.global [%0], [%1], 16;" :: "r"(dst), "l"(src))
#define CP_COMMIT() asm volatile("cp.async.commit_group;" ::: "memory")
#define CP_WAIT(n)  asm volatile("cp.async.wait_group %0;" :: "n"(n) : "memory")

// ---------------------------------------------------------------------------
// Packing into fp16 mma fragment order — coalesced (proven R11).
// ---------------------------------------------------------------------------
__global__ void pack_all(const float* __restrict__ x,
                         const float* __restrict__ Wq,
                         const float* __restrict__ Wk,
                         const float* __restrict__ Wv,
                         const float* __restrict__ Wo,
                         uint32_t* __restrict__ pX,
                         uint32_t* __restrict__ pW) {
  const int z = blockIdx.z;
  const int idx0 = blockIdx.x * blockDim.x + threadIdx.x;
  const int stride = gridDim.x * blockDim.x;
  if (z == 0) {
    for (int i = idx0; i < (MM / 16) * 64 * 32; i += stride) {
      int lane = i & 31, kt = (i >> 5) & 63, mt = i >> 11;
      int g7 = lane >> 2, t0 = lane & 3;
      const float* r0 = x + (size_t)(mt * 16 + g7) * DM + kt * 16 + 2 * t0;
      const float* r1 = r0 + 8 * DM;
      float2 a0 = *(const float2*)(r0);
      float2 a1 = *(const float2*)(r1);
      float2 a2 = *(const float2*)(r0 + 8);
      float2 a3 = *(const float2*)(r1 + 8);
      uint4 o = make_uint4(h2u(a0.x, a0.y), h2u(a1.x, a1.y),
                           h2u(a2.x, a2.y), h2u(a3.x, a3.y));
      *(uint4*)(pX + (size_t)((mt * 64 + kt) * 32 + lane) * 4) = o;
    }
  } else {
    const float* W = (z == 1) ? Wq : ((z == 2) ? Wk : ((z == 3) ? Wv : Wo));
    uint32_t* dst = pW + (size_t)(z - 1) * (DM * DM / 2);
    for (int i = idx0; i < (DM / 8) * 64 * 32; i += stride) {
      int lane = i & 31, kt = (i >> 5) & 63, nt = i >> 11;
      int g = lane >> 2, t0 = lane & 3;
      const float* rw = W + (size_t)(nt * 8 + g) * DM + kt * 16 + 2 * t0;
      float2 b0 = *(const float2*)(rw);
      float2 b1 = *(const float2*)(rw + 8);
      uint2 o = make_uint2(h2u(b0.x, b0.y), h2u(b1.x, b1.y));
      *(uint2*)(dst + (size_t)((nt * 64 + kt) * 64 + lane * 2)) = o;
    }
  }
}

// ---------------------------------------------------------------------------
// GEMM v6 (fp16 m16n8k16): block 128x64, 8 warps (4m x 2n), warp tile 32x32.
// ~70 regs -> 3 CTAs/SM (24 warps, 37.5% occ) for latency hiding.
// k-step 32, 4-stage cp.async (12KB/stage).
// modes: 0 plain fp32 [M,DM]; 2 head-split+rotate -> fp16 [B,H,T,Dh] (*scale);
//        3 head-split -> fp16 transposed [B,H,Dh,T] via smem-staged stores.
// ---------------------------------------------------------------------------
#define GSTG 12288
#define GEMM_SMEM (4 * GSTG)   // 49152

__global__ void __launch_bounds__(256, 3) gemm_fp16(
    const uint32_t* __restrict__ pA,
    const uint32_t* __restrict__ pB0, const uint32_t* __restrict__ pB1,
    const uint32_t* __restrict__ pB2,
    const float* __restrict__ bi0, const float* __restrict__ bi1,
    const float* __restrict__ bi2,
    void* __restrict__ o0, void* __restrict__ o1, void* __restrict__ o2,
    int md0, int md1, int md2, float sc0, float sc1, float sc2) {
  extern __shared__ __align__(16) char smem[];
  const int tid = threadIdx.x;
  const int w = tid >> 5, lane = tid & 31;
  const int r = lane >> 2, c = lane & 3;
  const int wm = w >> 1, wn = w & 1;
  const int z = blockIdx.z;
  const uint32_t* pB = (z == 0) ? pB0 : ((z == 1) ? pB1 : pB2);
  const float* bias = (z == 0) ? bi0 : ((z == 1) ? bi1 : bi2);
  void* out = (z == 0) ? o0 : ((z == 1) ? o1 : o2);
  const int mode = (z == 0) ? md0 : ((z == 1) ? md1 : md2);
  const float scale = (z == 0) ? sc0 : ((z == 1) ? sc1 : sc2);

  // block A: 8 m-tiles x 64 kt x 128 words; block B: 8 nt x 64 kt x 64 words
  const char* Ab = (const char*)(pA + ((size_t)blockIdx.y << 16));
  const char* Bb = (const char*)(pB + ((size_t)blockIdx.x << 15));
  const uint32_t sb = smem_u32(smem);

  float acc[2][4][4] = {};

  // One k32 stage: A 8KB (512 x 16B segs), B 4KB (256 x 16B segs).
  auto load_iter = [&](int it, int s) {
    uint32_t sa = sb + s * GSTG;
    const int it2 = it * 2;
#pragma unroll
    for (int i = 0; i < 2; i++) {
      int cid = tid + i * 256;                  // 0..511
      int mt = cid >> 6, ktl = (cid >> 5) & 1, off = cid & 31;
      CP_ASYNC16(sa + ((mt * 2 + ktl) * 32 + off) * 16,
                 Ab + ((size_t)(mt * 64 + it2 + ktl) * 32 + off) * 16);
    }
    {
      int cid = tid;                            // 0..255
      int nt = cid >> 5, ktl = (cid >> 4) & 1, seg = cid & 15;
      CP_ASYNC16(sa + 8192 + ((nt * 2 + ktl) * 16 + seg) * 16,
                 Bb + ((size_t)(nt * 64 + it2 + ktl) * 16 + seg) * 16);
    }
    CP_COMMIT();
  };

  load_iter(0, 0);
  load_iter(1, 1);
  load_iter(2, 2);

  for (int it = 0; it < 32; it++) {
    CP_WAIT(2);
    __syncthreads();
    const int nx = it + 3;
    if (nx < 32) load_iter(nx, nx & 3); else CP_COMMIT();
    const char* st = smem + (it & 3) * GSTG;
#pragma unroll
    for (int ktl = 0; ktl < 2; ktl++) {
      uint2 bfr[4];
#pragma unroll
      for (int n = 0; n < 4; n++)
        bfr[n] = *(const uint2*)(st + 8192 +
                                 ((wn * 4 + n) * 2 + ktl) * 256 + lane * 8);
      uint4 afr[2];
#pragma unroll
      for (int m = 0; m < 2; m++)
        afr[m] = *(const uint4*)(st +
                                 (((wm * 2 + m) * 2 + ktl) * 32 + lane) * 16);
#pragma unroll
      for (int n = 0; n < 4; n++)
#pragma unroll
        for (int m = 0; m < 2; m++)
          mma16(acc[m][n], (const unsigned*)&afr[m], bfr[n].x, bfr[n].y);
    }
  }

  if (mode == 3) {
    // V^T: stage fp16 [dh_local][t_local] tile (64 dh x 128 t) in smem
    // (272B rows), then coalesced 16B stores along t.
    CP_WAIT(0);
    __syncthreads();
#pragma unroll
    for (int m = 0; m < 2; m++) {
#pragma unroll
      for (int n = 0; n < 4; n++) {
        const int coll = (wn * 4 + n) * 8 + 2 * c;
        const int colg = blockIdx.x * 64 + coll;
        const float b0 = bias[colg], b1 = bias[colg + 1];
#pragma unroll
        for (int hf = 0; hf < 2; hf++) {
          const int rowl = (wm * 2 + m) * 16 + r + 8 * hf;
          __half h0 = __float2half_rn(acc[m][n][2 * hf] + b0);
          __half h1 = __float2half_rn(acc[m][n][2 * hf + 1] + b1);
          *(__half*)(smem + coll * 272 + rowl * 2) = h0;
          *(__half*)(smem + (coll + 1) * 272 + rowl * 2) = h1;
        }
      }
    }
    __syncthreads();
    uint16_t* vt = (uint16_t*)out;
    const int b_ = (blockIdx.y * 128) >> 11;
    const int t0g = (blockIdx.y * 128) & (TT - 1);
    // 64 dh-rows x 16 segs x 16B = full 128-t coverage (1024 ids)
#pragma unroll
    for (int i = 0; i < 4; i++) {
      int id = tid + i * 256;             // 0..1023
      int dhl = id >> 4, seg = id & 15;   // 64 dh-rows x 16 x 16B
      int colg = blockIdx.x * 64 + dhl;
      int h = colg >> 6, dh = colg & (DH - 1);
      uint4 v = *(const uint4*)(smem + dhl * 272 + seg * 16);
      *(uint4*)(vt + ((size_t)(b_ * NH + h) * DH + dh) * TT + t0g + seg * 8) = v;
    }
    return;
  }

  // epilogue (modes 0, 2)
#pragma unroll
  for (int m = 0; m < 2; m++) {
    const int row0 = blockIdx.y * 128 + (wm * 2 + m) * 16 + r;
#pragma unroll
    for (int n = 0; n < 4; n++) {
      const int col = blockIdx.x * 64 + (wn * 4 + n) * 8 + 2 * c;
      const float b0 = bias[col], b1 = bias[col + 1];
#pragma unroll
      for (int hf = 0; hf < 2; hf++) {
        const int row = row0 + 8 * hf;
        float v0 = acc[m][n][2 * hf] + b0;
        float v1 = acc[m][n][2 * hf + 1] + b1;
        if (mode == 0) {
          *(float2*)((float*)out + (size_t)row * DM + col) =
              make_float2(v0, v1);
        } else {  // mode 2: rotate_half + scale, fp16 [B,H,T,Dh]
          int b_ = row >> 11, t = row & (TT - 1);
          int h = col >> 6, dh = col & (DH - 1);
          float q0 = -v1 * scale, q1 = v0 * scale;
          ((uint32_t*)out)[((size_t)(b_ * NH + h) * TT + t) * 32 + (dh >> 1)] =
              h2u(q0, q1);
        }
      }
    }
  }
}

// ---------------------------------------------------------------------------
// Flash attention v6 (proven R13) + warp-level skip of fully-masked
// diagonal half-tiles (warps 0-3 on jt = 2qb+1).
// ---------------------------------------------------------------------------
#define HSTG 18432
#define STG128 36864
#define ATTN_SMEM (2 * STG128)   // 73728

__global__ void __launch_bounds__(256, 2) attn6(
    const uint32_t* __restrict__ Qw, const uint32_t* __restrict__ Kw,
    const uint16_t* __restrict__ Vt, uint32_t* __restrict__ pOut) {
  extern __shared__ __align__(16) char sm[];
  const uint32_t sb = smem_u32(sm);
  const int tid = threadIdx.x, w = tid >> 5, lane = tid & 31;
  const int r = lane >> 2, c = lane & 3;
  const int qb = gridDim.x - 1 - blockIdx.x;  // longest first
  const int bh = blockIdx.y;

  auto fill = [&](int jt128, int s) {
    const uint32_t base = sb + s * STG128;
    const uint32_t* Kg = Kw + ((size_t)(bh * TT + jt128 * 128)) * 32;
    const uint16_t* Vg = Vt + (size_t)bh * DH * TT + jt128 * 128;
#pragma unroll
    for (int i = 0; i < 4; i++) {
      int id = tid + i * 256;
      int row = id >> 3, sc = id & 7;
      int half = row >> 6, rl = row & 63;
      CP_ASYNC16(base + half * HSTG + rl * 144 + sc * 16,
                 Kg + row * 32 + sc * 4);
    }
#pragma unroll
    for (int i = 0; i < 4; i++) {
      int id = tid + i * 256;
      int sc = id & 7;
      int dh = (id >> 3) & 63, half = id >> 9;
      CP_ASYNC16(base + half * HSTG + 9216 + dh * 144 + sc * 16,
                 Vg + (size_t)dh * TT + half * 64 + sc * 8);
    }
    CP_COMMIT();
  };

  const uint32_t* Qu = Qw + ((size_t)bh * TT + qb * 128 + 16 * w) * 32;
  unsigned qa[4][4];
#pragma unroll
  for (int kc = 0; kc < 4; kc++) {
    qa[kc][0] = Qu[r * 32 + 8 * kc + c];
    qa[kc][1] = Qu[(r + 8) * 32 + 8 * kc + c];
    qa[kc][2] = Qu[r * 32 + 8 * kc + c + 4];
    qa[kc][3] = Qu[(r + 8) * 32 + 8 * kc + c + 4];
  }

  float o[8][4] = {};
  float mrow[2] = {-1e30f, -1e30f}, lrow[2] = {0.f, 0.f};

  const int nkt = qb + 1;   // 128-key iterations
  fill(0, 0);

  for (int jt128 = 0; jt128 < nkt; jt128++) {
    const int s = jt128 & 1;
    __syncthreads();
    if (jt128 + 1 < nkt) {
      fill(jt128 + 1, s ^ 1);
      CP_WAIT(1);
    } else {
      CP_WAIT(0);
    }
    __syncthreads();

#pragma unroll
    for (int half = 0; half < 2; half++) {
      const int jt = 2 * jt128 + half;
      // warp-level skip: this 64-key tile entirely above the causal
      // boundary for every row this warp owns -> zero contribution.
      if (jt * 64 > qb * 128 + 16 * w + 15) continue;
      const char* kbuf = sm + s * STG128 + half * HSTG;
      const char* vbuf = kbuf + 9216;

      float sacc[8][4] = {};
#pragma unroll
      for (int kc = 0; kc < 4; kc++) {
#pragma unroll
        for (int ni = 0; ni < 8; ni++) {
          const uint32_t* bp =
              (const uint32_t*)(kbuf + (8 * ni + r) * 144 + (8 * kc + c) * 4);
          mma16(sacc[ni], qa[kc], bp[0], bp[4]);
        }
      }

      if (jt >= 2 * qb) {  // diagonal tiles: causal mask
        const int qrow0 = qb * 128 + 16 * w + r;
#pragma unroll
        for (int ni = 0; ni < 8; ni++) {
          const int key0 = jt * 64 + 8 * ni + 2 * c;
#pragma unroll
          for (int reg = 0; reg < 4; reg++) {
            int key = key0 + (reg & 1);
            int qr = qrow0 + 8 * (reg >> 1);
            if (key > qr) sacc[ni][reg] = -1e30f;
          }
        }
      }

#pragma unroll
      for (int h = 0; h < 2; h++) {
        float mx = -1e30f;
#pragma unroll
        for (int ni = 0; ni < 8; ni++)
          mx = fmaxf(mx, fmaxf(sacc[ni][2 * h], sacc[ni][2 * h + 1]));
        mx = fmaxf(mx, __shfl_xor_sync(0xffffffffu, mx, 1));
        mx = fmaxf(mx, __shfl_xor_sync(0xffffffffu, mx, 2));
        float mnew = fmaxf(mrow[h], mx);
        float corr = exp2f(mrow[h] - mnew);
        mrow[h] = mnew;
        float rs = 0.f;
#pragma unroll
        for (int ni = 0; ni < 8; ni++) {
          sacc[ni][2 * h] = exp2f(sacc[ni][2 * h] - mnew);
          sacc[ni][2 * h + 1] = exp2f(sacc[ni][2 * h + 1] - mnew);
          rs += sacc[ni][2 * h] + sacc[ni][2 * h + 1];
        }
        rs += __shfl_xor_sync(0xffffffffu, rs, 1);
        rs += __shfl_xor_sync(0xffffffffu, rs, 2);
        lrow[h] = lrow[h] * corr + rs;
#pragma unroll
        for (int ni = 0; ni < 8; ni++) {
          o[ni][2 * h] *= corr;
          o[ni][2 * h + 1] *= corr;
        }
      }

      // O += P @ V (QK C-frag == PV A-frag; register-resident P)
#pragma unroll
      for (int kc = 0; kc < 4; kc++) {
        unsigned pa[4];
        pa[0] = h2u(sacc[2 * kc][0], sacc[2 * kc][1]);
        pa[1] = h2u(sacc[2 * kc][2], sacc[2 * kc][3]);
        pa[2] = h2u(sacc[2 * kc + 1][0], sacc[2 * kc + 1][1]);
        pa[3] = h2u(sacc[2 * kc + 1][2], sacc[2 * kc + 1][3]);
#pragma unroll
        for (int ni = 0; ni < 8; ni++) {
          const uint32_t* vp =
              (const uint32_t*)(vbuf + (8 * ni + r) * 144 + (8 * kc + c) * 4);
          mma16(o[ni], pa, vp[0], vp[4]);
        }
      }
    }
  }

  // epilogue: normalize, fp16 packed-A fragments, uint4 stores (proven R11)
  const int b_ = bh >> 4, hh = bh & (NH - 1);
  const int mtile = b_ * 128 + qb * 8 + w;
  const float inv0 = 1.0f / lrow[0], inv1 = 1.0f / lrow[1];
#pragma unroll
  for (int k2 = 0; k2 < 4; k2++) {
    const int kt = hh * 4 + k2;
    uint4 ov = make_uint4(
        h2u(o[2 * k2][0] * inv0, o[2 * k2][1] * inv0),
        h2u(o[2 * k2][2] * inv1, o[2 * k2][3] * inv1),
        h2u(o[2 * k2 + 1][0] * inv0, o[2 * k2 + 1][1] * inv0),
        h2u(o[2 * k2 + 1][2] * inv1, o[2 * k2 + 1][3] * inv1));
    *(uint4*)(pOut + (size_t)((mtile * 64 + kt) * 32 + lane) * 4) = ov;
  }
}

extern "C" void kernel_launch(void* const* d_in, const int* in_sizes, int n_in,
                              void* d_out, int out_size) {
  const float* x  = (const float*)d_in[0];
  const float* Wq = (const float*)d_in[1];
  const float* bq = (const float*)d_in[2];
  const float* Wk = (const float*)d_in[3];
  const float* bk = (const float*)d_in[4];
  const float* Wv = (const float*)d_in[5];
  const float* bv = (const float*)d_in[6];
  const float* Wo = (const float*)d_in[7];
  const float* bo = (const float*)d_in[8];
  float* out = (float*)d_out;

  uint32_t *qp, *kp, *ap, *xp, *wp;
  uint16_t *vtp;
  cudaGetSymbolAddress((void**)&qp, g_q);
  cudaGetSymbolAddress((void**)&kp, g_k);
  cudaGetSymbolAddress((void**)&vtp, g_vt);
  cudaGetSymbolAddress((void**)&ap, g_attp);
  cudaGetSymbolAddress((void**)&xp, g_xp);
  cudaGetSymbolAddress((void**)&wp, g_wp);

  static int attr_set = 0;
  if (!attr_set) {
    cudaFuncSetAttribute(gemm_fp16, cudaFuncAttributeMaxDynamicSharedMemorySize,
                         GEMM_SMEM);
    cudaFuncSetAttribute(attn6, cudaFuncAttributeMaxDynamicSharedMemorySize,
                         ATTN_SMEM);
    attr_set = 1;
  }

  const float QSCALE = 0.125f * 1.4426950408889634f;  // 1/sqrt(Dh) * log2(e)
  const size_t WSZ = (size_t)DM * DM / 2;             // words per packed W

  // 1) pack inputs into fp16 fragment layouts (coalesced)
  pack_all<<<dim3(512, 1, 5), 256>>>(x, Wq, Wk, Wv, Wo, xp, wp);

  // 2) fused QKV: Q,K -> fp16 rot (+Q scale); V -> fp16 transposed (staged)
  gemm_fp16<<<dim3(16, 32, 3), 256, GEMM_SMEM>>>(
      xp, wp, wp + WSZ, wp + 2 * WSZ, bq, bk, bv, qp, kp, vtp,
      2, 2, 3, QSCALE, 1.f, 1.f);

  // 3) attention (128-key stages, register-resident P, masked-tile skip)
  attn6<<<dim3(16, 32), 256, ATTN_SMEM>>>(qp, kp, vtp, ap);

  // 4) output projection (fp32 out)
  gemm_fp16<<<dim3(16, 32, 1), 256, GEMM_SMEM>>>(
      ap, wp + 3 * WSZ, wp + 3 * WSZ, wp + 3 * WSZ, bo, bo, bo, out, out, out,
      0, 0, 0, 1.f, 1.f, 1.f);
}

// round 15
// speedup vs baseline: 1.0069x; 1.0069x over previous
#include <cuda_runtime.h>
#include <cuda_fp16.h>
#include <cstdint>

#define BB 2
#define TT 2048
#define DM 1024
#define NH 16
#define DH 64
#define MM (BB * TT)   // 4096

// Scratch (device globals; no allocation allowed)
__device__ uint32_t g_q[BB * NH * TT * (DH / 2)];   // fp16 [B,H,T,Dh], *0.125*log2e
__device__ uint32_t g_k[BB * NH * TT * (DH / 2)];   // fp16 [B,H,T,Dh]
__device__ uint16_t g_vt[BB * NH * DH * TT];        // fp16 [B,H,Dh,T] (transposed)
__device__ uint32_t g_attp[MM * DM / 2];            // attn out, fp16 packed-A frags
__device__ uint32_t g_xp[MM * DM / 2];              // x fp16 packed-A frags
__device__ uint32_t g_wp[4 * DM * DM / 2];          // W's fp16 packed-B frags

// ---------------------------------------------------------------------------
// helpers
// ---------------------------------------------------------------------------
__device__ __forceinline__ uint32_t smem_u32(const void* p) {
  uint32_t a;
  asm("{ .reg .u64 t; cvta.to.shared.u64 t, %1; cvt.u32.u64 %0, t; }"
      : "=r"(a) : "l"(p));
  return a;
}

__device__ __forceinline__ uint32_t h2u(float lo, float hi) {
  __half2 h = __floats2half2_rn(lo, hi);
  return *reinterpret_cast<uint32_t*>(&h);
}

// fp16 m16n8k16
__device__ __forceinline__ void mma16(float* c, const unsigned* a,
                                      unsigned b0, unsigned b1) {
  asm("mma.sync.aligned.m16n8k16.row.col.f32.f16.f16.f32 "
      "{%0,%1,%2,%3},{%4,%5,%6,%7},{%8,%9},{%0,%1,%2,%3};"
      : "+f"(c[0]), "+f"(c[1]), "+f"(c[2]), "+f"(c[3])
      : "r"(a[0]), "r"(a[1]), "r"(a[2]), "r"(a[3]), "r"(b0), "r"(b1));
}

#define CP_ASYNC16(dst, src) \
  asm volatile("cp.async.cg.shared.global [%0], [%1], 16;" :: "r"(dst), "l"(src))
#define CP_COMMIT() asm volatile("cp.async.commit_group;" ::: "memory")
#define CP_WAIT(n)  asm volatile("cp.async.wait_group %0;" :: "n"(n) : "memory")

// ---------------------------------------------------------------------------
// Packing into fp16 mma fragment order — coalesced (proven R11).
// ---------------------------------------------------------------------------
__global__ void pack_all(const float* __restrict__ x,
                         const float* __restrict__ Wq,
                         const float* __restrict__ Wk,
                         const float* __restrict__ Wv,
                         const float* __restrict__ Wo,
                         uint32_t* __restrict__ pX,
                         uint32_t* __restrict__ pW) {
  const int z = blockIdx.z;
  const int idx0 = blockIdx.x * blockDim.x + threadIdx.x;
  const int stride = gridDim.x * blockDim.x;
  if (z == 0) {
    for (int i = idx0; i < (MM / 16) * 64 * 32; i += stride) {
      int lane = i & 31, kt = (i >> 5) & 63, mt = i >> 11;
      int g7 = lane >> 2, t0 = lane & 3;
      const float* r0 = x + (size_t)(mt * 16 + g7) * DM + kt * 16 + 2 * t0;
      const float* r1 = r0 + 8 * DM;
      float2 a0 = *(const float2*)(r0);
      float2 a1 = *(const float2*)(r1);
      float2 a2 = *(const float2*)(r0 + 8);
      float2 a3 = *(const float2*)(r1 + 8);
      uint4 o = make_uint4(h2u(a0.x, a0.y), h2u(a1.x, a1.y),
                           h2u(a2.x, a2.y), h2u(a3.x, a3.y));
      *(uint4*)(pX + (size_t)((mt * 64 + kt) * 32 + lane) * 4) = o;
    }
  } else {
    const float* W = (z == 1) ? Wq : ((z == 2) ? Wk : ((z == 3) ? Wv : Wo));
    uint32_t* dst = pW + (size_t)(z - 1) * (DM * DM / 2);
    for (int i = idx0; i < (DM / 8) * 64 * 32; i += stride) {
      int lane = i & 31, kt = (i >> 5) & 63, nt = i >> 11;
      int g = lane >> 2, t0 = lane & 3;
      const float* rw = W + (size_t)(nt * 8 + g) * DM + kt * 16 + 2 * t0;
      float2 b0 = *(const float2*)(rw);
      float2 b1 = *(const float2*)(rw + 8);
      uint2 o = make_uint2(h2u(b0.x, b0.y), h2u(b1.x, b1.y));
      *(uint2*)(dst + (size_t)((nt * 64 + kt) * 64 + lane * 2)) = o;
    }
  }
}

// ---------------------------------------------------------------------------
// GEMM (fp16 m16n8k16) — exact R13 config (proven fastest: 29.6us O-proj).
// Block 128x128, 8 warps (2m x 4n), warp tile 64x32, k-step 32,
// 4-stage cp.async (16KB/stage), 2 CTAs/SM.
// modes: 0 plain fp32 [M,DM]; 2 head-split+rotate -> fp16 [B,H,T,Dh] (*scale);
//        3 head-split -> fp16 transposed [B,H,Dh,T] via smem-staged stores.
// ---------------------------------------------------------------------------
#define GSTG 16384
#define GEMM_SMEM (4 * GSTG)   // 65536

__global__ void __launch_bounds__(256, 2) gemm_fp16(
    const uint32_t* __restrict__ pA,
    const uint32_t* __restrict__ pB0, const uint32_t* __restrict__ pB1,
    const uint32_t* __restrict__ pB2,
    const float* __restrict__ bi0, const float* __restrict__ bi1,
    const float* __restrict__ bi2,
    void* __restrict__ o0, void* __restrict__ o1, void* __restrict__ o2,
    int md0, int md1, int md2, float sc0, float sc1, float sc2) {
  extern __shared__ __align__(16) char smem[];
  const int tid = threadIdx.x;
  const int w = tid >> 5, lane = tid & 31;
  const int r = lane >> 2, c = lane & 3;
  const int wm = w >> 2, wn = w & 3;
  const int z = blockIdx.z;
  const uint32_t* pB = (z == 0) ? pB0 : ((z == 1) ? pB1 : pB2);
  const float* bias = (z == 0) ? bi0 : ((z == 1) ? bi1 : bi2);
  void* out = (z == 0) ? o0 : ((z == 1) ? o1 : o2);
  const int mode = (z == 0) ? md0 : ((z == 1) ? md1 : md2);
  const float scale = (z == 0) ? sc0 : ((z == 1) ? sc1 : sc2);

  const char* Ab = (const char*)(pA + ((size_t)blockIdx.y << 16));
  const char* Bb = (const char*)(pB + ((size_t)blockIdx.x << 16));
  const uint32_t sb = smem_u32(smem);

  float acc[4][4][4] = {};

  auto load_iter = [&](int it, int s) {
    uint32_t sa = sb + s * GSTG;
    const int it2 = it * 2;
#pragma unroll
    for (int i = 0; i < 2; i++) {
      int cid = tid + i * 256;
      int mt = cid >> 6, ktl = (cid >> 5) & 1, off = cid & 31;
      CP_ASYNC16(sa + ((mt * 2 + ktl) * 32 + off) * 16,
                 Ab + ((size_t)(mt * 64 + it2 + ktl) * 32 + off) * 16);
    }
#pragma unroll
    for (int i = 0; i < 2; i++) {
      int cid = tid + i * 256;
      int nt = cid >> 5, ktl = (cid >> 4) & 1, off = cid & 15;
      CP_ASYNC16(sa + 8192 + ((nt * 2 + ktl) * 16 + off) * 16,
                 Bb + ((size_t)(nt * 64 + it2 + ktl) * 16 + off) * 16);
    }
    CP_COMMIT();
  };

  load_iter(0, 0);
  load_iter(1, 1);
  load_iter(2, 2);

  for (int it = 0; it < 32; it++) {
    CP_WAIT(2);
    __syncthreads();
    const int nx = it + 3;
    if (nx < 32) load_iter(nx, nx & 3); else CP_COMMIT();
    const char* st = smem + (it & 3) * GSTG;
#pragma unroll
    for (int ktl = 0; ktl < 2; ktl++) {
      uint2 bfr[4];
#pragma unroll
      for (int n = 0; n < 4; n++)
        bfr[n] = *(const uint2*)(st + 8192 +
                                 (((wn * 4 + n) * 2 + ktl) * 32 + lane) * 8);
      uint4 afr[4];
#pragma unroll
      for (int m = 0; m < 4; m++)
        afr[m] = *(const uint4*)(st +
                                 (((wm * 4 + m) * 2 + ktl) * 32 + lane) * 16);
#pragma unroll
      for (int n = 0; n < 4; n++)
#pragma unroll
        for (int m = 0; m < 4; m++)
          mma16(acc[m][n], (const unsigned*)&afr[m], bfr[n].x, bfr[n].y);
    }
  }

  if (mode == 3) {
    // V^T: stage fp16 [dh_local][t_local] tile in smem (272B rows), then
    // coalesced 16B stores along t.  Tile = 128 dh x 128 t.
    CP_WAIT(0);
    __syncthreads();
#pragma unroll
    for (int m = 0; m < 4; m++) {
#pragma unroll
      for (int n = 0; n < 4; n++) {
        const int coll = (wn * 4 + n) * 8 + 2 * c;
        const int colg = blockIdx.x * 128 + coll;
        const float b0 = bias[colg], b1 = bias[colg + 1];
#pragma unroll
        for (int hf = 0; hf < 2; hf++) {
          const int rowl = (wm * 4 + m) * 16 + r + 8 * hf;
          __half h0 = __float2half_rn(acc[m][n][2 * hf] + b0);
          __half h1 = __float2half_rn(acc[m][n][2 * hf + 1] + b1);
          *(__half*)(smem + coll * 272 + rowl * 2) = h0;
          *(__half*)(smem + (coll + 1) * 272 + rowl * 2) = h1;
        }
      }
    }
    __syncthreads();
    uint16_t* vt = (uint16_t*)out;
    const int b_ = (blockIdx.y * 128) >> 11;
    const int t0g = (blockIdx.y * 128) & (TT - 1);
    // 128 dh-rows x 16 segs x 16B = full 128-t coverage (2048 ids)
#pragma unroll
    for (int i = 0; i < 8; i++) {
      int id = tid + i * 256;             // 0..2047
      int dhl = id >> 4, seg = id & 15;   // 128 dh-rows x 16 x 16B
      int colg = blockIdx.x * 128 + dhl;
      int h = colg >> 6, dh = colg & (DH - 1);
      uint4 v = *(const uint4*)(smem + dhl * 272 + seg * 16);
      *(uint4*)(vt + ((size_t)(b_ * NH + h) * DH + dh) * TT + t0g + seg * 8) = v;
    }
    return;
  }

  // epilogue (modes 0, 2)
#pragma unroll
  for (int m = 0; m < 4; m++) {
    const int row0 = blockIdx.y * 128 + (wm * 4 + m) * 16 + r;
#pragma unroll
    for (int n = 0; n < 4; n++) {
      const int col = blockIdx.x * 128 + (wn * 4 + n) * 8 + 2 * c;
      const float b0 = bias[col], b1 = bias[col + 1];
#pragma unroll
      for (int hf = 0; hf < 2; hf++) {
        const int row = row0 + 8 * hf;
        float v0 = acc[m][n][2 * hf] + b0;
        float v1 = acc[m][n][2 * hf + 1] + b1;
        if (mode == 0) {
          *(float2*)((float*)out + (size_t)row * DM + col) =
              make_float2(v0, v1);
        } else {  // mode 2: rotate_half + scale, fp16 [B,H,T,Dh]
          int b_ = row >> 11, t = row & (TT - 1);
          int h = col >> 6, dh = col & (DH - 1);
          float q0 = -v1 * scale, q1 = v0 * scale;
          ((uint32_t*)out)[((size_t)(b_ * NH + h) * TT + t) * 32 + (dh >> 1)] =
              h2u(q0, q1);
        }
      }
    }
  }
}

// ---------------------------------------------------------------------------
// Flash attention v6 (proven R13) + warp-level skip of fully-masked
// diagonal half-tiles (kept from R14 — correct, same rel_err).
// ---------------------------------------------------------------------------
#define HSTG 18432
#define STG128 36864
#define ATTN_SMEM (2 * STG128)   // 73728

__global__ void __launch_bounds__(256, 2) attn6(
    const uint32_t* __restrict__ Qw, const uint32_t* __restrict__ Kw,
    const uint16_t* __restrict__ Vt, uint32_t* __restrict__ pOut) {
  extern __shared__ __align__(16) char sm[];
  const uint32_t sb = smem_u32(sm);
  const int tid = threadIdx.x, w = tid >> 5, lane = tid & 31;
  const int r = lane >> 2, c = lane & 3;
  const int qb = gridDim.x - 1 - blockIdx.x;  // longest first
  const int bh = blockIdx.y;

  auto fill = [&](int jt128, int s) {
    const uint32_t base = sb + s * STG128;
    const uint32_t* Kg = Kw + ((size_t)(bh * TT + jt128 * 128)) * 32;
    const uint16_t* Vg = Vt + (size_t)bh * DH * TT + jt128 * 128;
#pragma unroll
    for (int i = 0; i < 4; i++) {
      int id = tid + i * 256;
      int row = id >> 3, sc = id & 7;
      int half = row >> 6, rl = row & 63;
      CP_ASYNC16(base + half * HSTG + rl * 144 + sc * 16,
                 Kg + row * 32 + sc * 4);
    }
#pragma unroll
    for (int i = 0; i < 4; i++) {
      int id = tid + i * 256;
      int sc = id & 7;
      int dh = (id >> 3) & 63, half = id >> 9;
      CP_ASYNC16(base + half * HSTG + 9216 + dh * 144 + sc * 16,
                 Vg + (size_t)dh * TT + half * 64 + sc * 8);
    }
    CP_COMMIT();
  };

  const uint32_t* Qu = Qw + ((size_t)bh * TT + qb * 128 + 16 * w) * 32;
  unsigned qa[4][4];
#pragma unroll
  for (int kc = 0; kc < 4; kc++) {
    qa[kc][0] = Qu[r * 32 + 8 * kc + c];
    qa[kc][1] = Qu[(r + 8) * 32 + 8 * kc + c];
    qa[kc][2] = Qu[r * 32 + 8 * kc + c + 4];
    qa[kc][3] = Qu[(r + 8) * 32 + 8 * kc + c + 4];
  }

  float o[8][4] = {};
  float mrow[2] = {-1e30f, -1e30f}, lrow[2] = {0.f, 0.f};

  const int nkt = qb + 1;   // 128-key iterations
  fill(0, 0);

  for (int jt128 = 0; jt128 < nkt; jt128++) {
    const int s = jt128 & 1;
    __syncthreads();
    if (jt128 + 1 < nkt) {
      fill(jt128 + 1, s ^ 1);
      CP_WAIT(1);
    } else {
      CP_WAIT(0);
    }
    __syncthreads();

#pragma unroll
    for (int half = 0; half < 2; half++) {
      const int jt = 2 * jt128 + half;
      // warp-level skip: tile entirely above the causal boundary for all
      // rows this warp owns -> zero contribution (corr=1, adds 0).
      if (jt * 64 > qb * 128 + 16 * w + 15) continue;
      const char* kbuf = sm + s * STG128 + half * HSTG;
      const char* vbuf = kbuf + 9216;

      float sacc[8][4] = {};
#pragma unroll
      for (int kc = 0; kc < 4; kc++) {
#pragma unroll
        for (int ni = 0; ni < 8; ni++) {
          const uint32_t* bp =
              (const uint32_t*)(kbuf + (8 * ni + r) * 144 + (8 * kc + c) * 4);
          mma16(sacc[ni], qa[kc], bp[0], bp[4]);
        }
      }

      if (jt >= 2 * qb) {  // diagonal tiles: causal mask
        const int qrow0 = qb * 128 + 16 * w + r;
#pragma unroll
        for (int ni = 0; ni < 8; ni++) {
          const int key0 = jt * 64 + 8 * ni + 2 * c;
#pragma unroll
          for (int reg = 0; reg < 4; reg++) {
            int key = key0 + (reg & 1);
            int qr = qrow0 + 8 * (reg >> 1);
            if (key > qr) sacc[ni][reg] = -1e30f;
          }
        }
      }

#pragma unroll
      for (int h = 0; h < 2; h++) {
        float mx = -1e30f;
#pragma unroll
        for (int ni = 0; ni < 8; ni++)
          mx = fmaxf(mx, fmaxf(sacc[ni][2 * h], sacc[ni][2 * h + 1]));
        mx = fmaxf(mx, __shfl_xor_sync(0xffffffffu, mx, 1));
        mx = fmaxf(mx, __shfl_xor_sync(0xffffffffu, mx, 2));
        float mnew = fmaxf(mrow[h], mx);
        float corr = exp2f(mrow[h] - mnew);
        mrow[h] = mnew;
        float rs = 0.f;
#pragma unroll
        for (int ni = 0; ni < 8; ni++) {
          sacc[ni][2 * h] = exp2f(sacc[ni][2 * h] - mnew);
          sacc[ni][2 * h + 1] = exp2f(sacc[ni][2 * h + 1] - mnew);
          rs += sacc[ni][2 * h] + sacc[ni][2 * h + 1];
        }
        rs += __shfl_xor_sync(0xffffffffu, rs, 1);
        rs += __shfl_xor_sync(0xffffffffu, rs, 2);
        lrow[h] = lrow[h] * corr + rs;
#pragma unroll
        for (int ni = 0; ni < 8; ni++) {
          o[ni][2 * h] *= corr;
          o[ni][2 * h + 1] *= corr;
        }
      }

      // O += P @ V (QK C-frag == PV A-frag; register-resident P)
#pragma unroll
      for (int kc = 0; kc < 4; kc++) {
        unsigned pa[4];
        pa[0] = h2u(sacc[2 * kc][0], sacc[2 * kc][1]);
        pa[1] = h2u(sacc[2 * kc][2], sacc[2 * kc][3]);
        pa[2] = h2u(sacc[2 * kc + 1][0], sacc[2 * kc + 1][1]);
        pa[3] = h2u(sacc[2 * kc + 1][2], sacc[2 * kc + 1][3]);
#pragma unroll
        for (int ni = 0; ni < 8; ni++) {
          const uint32_t* vp =
              (const uint32_t*)(vbuf + (8 * ni + r) * 144 + (8 * kc + c) * 4);
          mma16(o[ni], pa, vp[0], vp[4]);
        }
      }
    }
  }

  // epilogue: normalize, fp16 packed-A fragments, uint4 stores (proven R11)
  const int b_ = bh >> 4, hh = bh & (NH - 1);
  const int mtile = b_ * 128 + qb * 8 + w;
  const float inv0 = 1.0f / lrow[0], inv1 = 1.0f / lrow[1];
#pragma unroll
  for (int k2 = 0; k2 < 4; k2++) {
    const int kt = hh * 4 + k2;
    uint4 ov = make_uint4(
        h2u(o[2 * k2][0] * inv0, o[2 * k2][1] * inv0),
        h2u(o[2 * k2][2] * inv1, o[2 * k2][3] * inv1),
        h2u(o[2 * k2 + 1][0] * inv0, o[2 * k2 + 1][1] * inv0),
        h2u(o[2 * k2 + 1][2] * inv1, o[2 * k2 + 1][3] * inv1));
    *(uint4*)(pOut + (size_t)((mtile * 64 + kt) * 32 + lane) * 4) = ov;
  }
}

extern "C" void kernel_launch(void* const* d_in, const int* in_sizes, int n_in,
                              void* d_out, int out_size) {
  const float* x  = (const float*)d_in[0];
  const float* Wq = (const float*)d_in[1];
  const float* bq = (const float*)d_in[2];
  const float* Wk = (const float*)d_in[3];
  const float* bk = (const float*)d_in[4];
  const float* Wv = (const float*)d_in[5];
  const float* bv = (const float*)d_in[6];
  const float* Wo = (const float*)d_in[7];
  const float* bo = (const float*)d_in[8];
  float* out = (float*)d_out;

  uint32_t *qp, *kp, *ap, *xp, *wp;
  uint16_t *vtp;
  cudaGetSymbolAddress((void**)&qp, g_q);
  cudaGetSymbolAddress((void**)&kp, g_k);
  cudaGetSymbolAddress((void**)&vtp, g_vt);
  cudaGetSymbolAddress((void**)&ap, g_attp);
  cudaGetSymbolAddress((void**)&xp, g_xp);
  cudaGetSymbolAddress((void**)&wp, g_wp);

  static int attr_set = 0;
  if (!attr_set) {
    cudaFuncSetAttribute(gemm_fp16, cudaFuncAttributeMaxDynamicSharedMemorySize,
                         GEMM_SMEM);
    cudaFuncSetAttribute(attn6, cudaFuncAttributeMaxDynamicSharedMemorySize,
                         ATTN_SMEM);
    attr_set = 1;
  }

  const float QSCALE = 0.125f * 1.4426950408889634f;  // 1/sqrt(Dh) * log2(e)
  const size_t WSZ = (size_t)DM * DM / 2;             // words per packed W

  // 1) pack inputs into fp16 fragment layouts (coalesced)
  pack_all<<<dim3(512, 1, 5), 256>>>(x, Wq, Wk, Wv, Wo, xp, wp);

  // 2) fused QKV: Q,K -> fp16 rot (+Q scale); V -> fp16 transposed (staged)
  gemm_fp16<<<dim3(8, 32, 3), 256, GEMM_SMEM>>>(
      xp, wp, wp + WSZ, wp + 2 * WSZ, bq, bk, bv, qp, kp, vtp,
      2, 2, 3, QSCALE, 1.f, 1.f);

  // 3) attention (128-key stages, register-resident P, masked-tile skip)
  attn6<<<dim3(16, 32), 256, ATTN_SMEM>>>(qp, kp, vtp, ap);

  // 4) output projection (fp32 out)
  gemm_fp16<<<dim3(8, 32, 1), 256, GEMM_SMEM>>>(
      ap, wp + 3 * WSZ, wp + 3 * WSZ, wp + 3 * WSZ, bo, bo, bo, out, out, out,
      0, 0, 0, 1.f, 1.f, 1.f);
}

// round 16
// speedup vs baseline: 1.0437x; 1.0366x over previous
#include <cuda_runtime.h>
#include <cuda_fp16.h>
#include <cstdint>

#define BB 2
#define TT 2048
#define DM 1024
#define NH 16
#define DH 64
#define MM (BB * TT)   // 4096

// Scratch (device globals; no allocation allowed)
__device__ uint32_t g_q[BB * NH * TT * (DH / 2)];   // fp16 [B,H,T,Dh], *0.125*log2e
__device__ uint32_t g_k[BB * NH * TT * (DH / 2)];   // fp16 [B,H,T,Dh]
__device__ uint16_t g_vt[BB * NH * DH * TT];        // fp16 [B,H,Dh,T] (transposed)
__device__ uint32_t g_attp[MM * DM / 2];            // attn out, fp16 packed-A frags
__device__ uint32_t g_xp[MM * DM / 2];              // x fp16 packed-A frags
__device__ uint32_t g_wp[4 * DM * DM / 2];          // W's fp16 packed-B frags

// ---------------------------------------------------------------------------
// helpers
// ---------------------------------------------------------------------------
__device__ __forceinline__ uint32_t smem_u32(const void* p) {
  uint32_t a;
  asm("{ .reg .u64 t; cvta.to.shared.u64 t, %1; cvt.u32.u64 %0, t; }"
      : "=r"(a) : "l"(p));
  return a;
}

__device__ __forceinline__ uint32_t h2u(float lo, float hi) {
  __half2 h = __floats2half2_rn(lo, hi);
  return *reinterpret_cast<uint32_t*>(&h);
}

// fp16 m16n8k16
__device__ __forceinline__ void mma16(float* c, const unsigned* a,
                                      unsigned b0, unsigned b1) {
  asm("mma.sync.aligned.m16n8k16.row.col.f32.f16.f16.f32 "
      "{%0,%1,%2,%3},{%4,%5,%6,%7},{%8,%9},{%0,%1,%2,%3};"
      : "+f"(c[0]), "+f"(c[1]), "+f"(c[2]), "+f"(c[3])
      : "r"(a[0]), "r"(a[1]), "r"(a[2]), "r"(a[3]), "r"(b0), "r"(b1));
}

#define CP_ASYNC16(dst, src) \
  asm volatile("cp.async.cg.shared.global [%0], [%1], 16;" :: "r"(dst), "l"(src))
#define CP_COMMIT() asm volatile("cp.async.commit_group;" ::: "memory")
#define CP_WAIT(n)  asm volatile("cp.async.wait_group %0;" :: "n"(n) : "memory")

// ---------------------------------------------------------------------------
// Packing into fp16 mma fragment order — coalesced (proven R11).
// ---------------------------------------------------------------------------
__global__ void pack_all(const float* __restrict__ x,
                         const float* __restrict__ Wq,
                         const float* __restrict__ Wk,
                         const float* __restrict__ Wv,
                         const float* __restrict__ Wo,
                         uint32_t* __restrict__ pX,
                         uint32_t* __restrict__ pW) {
  const int z = blockIdx.z;
  const int idx0 = blockIdx.x * blockDim.x + threadIdx.x;
  const int stride = gridDim.x * blockDim.x;
  if (z == 0) {
    for (int i = idx0; i < (MM / 16) * 64 * 32; i += stride) {
      int lane = i & 31, kt = (i >> 5) & 63, mt = i >> 11;
      int g7 = lane >> 2, t0 = lane & 3;
      const float* r0 = x + (size_t)(mt * 16 + g7) * DM + kt * 16 + 2 * t0;
      const float* r1 = r0 + 8 * DM;
      float2 a0 = *(const float2*)(r0);
      float2 a1 = *(const float2*)(r1);
      float2 a2 = *(const float2*)(r0 + 8);
      float2 a3 = *(const float2*)(r1 + 8);
      uint4 o = make_uint4(h2u(a0.x, a0.y), h2u(a1.x, a1.y),
                           h2u(a2.x, a2.y), h2u(a3.x, a3.y));
      *(uint4*)(pX + (size_t)((mt * 64 + kt) * 32 + lane) * 4) = o;
    }
  } else {
    const float* W = (z == 1) ? Wq : ((z == 2) ? Wk : ((z == 3) ? Wv : Wo));
    uint32_t* dst = pW + (size_t)(z - 1) * (DM * DM / 2);
    for (int i = idx0; i < (DM / 8) * 64 * 32; i += stride) {
      int lane = i & 31, kt = (i >> 5) & 63, nt = i >> 11;
      int g = lane >> 2, t0 = lane & 3;
      const float* rw = W + (size_t)(nt * 8 + g) * DM + kt * 16 + 2 * t0;
      float2 b0 = *(const float2*)(rw);
      float2 b1 = *(const float2*)(rw + 8);
      uint2 o = make_uint2(h2u(b0.x, b0.y), h2u(b1.x, b1.y));
      *(uint2*)(dst + (size_t)((nt * 64 + kt) * 64 + lane * 2)) = o;
    }
  }
}

// ---------------------------------------------------------------------------
// GEMM (fp16 m16n8k16) — proven-best R13 config (29.6us O-proj).
// Block 128x128, 8 warps (2m x 4n), warp tile 64x32, k-step 32,
// 4-stage cp.async (16KB/stage), 2 CTAs/SM.
// modes: 0 plain fp32 [M,DM]; 2 head-split+rotate -> fp16 [B,H,T,Dh] (*scale);
//        3 head-split -> fp16 transposed [B,H,Dh,T] via smem-staged stores.
// ---------------------------------------------------------------------------
#define GSTG 16384
#define GEMM_SMEM (4 * GSTG)   // 65536

__global__ void __launch_bounds__(256, 2) gemm_fp16(
    const uint32_t* __restrict__ pA,
    const uint32_t* __restrict__ pB0, const uint32_t* __restrict__ pB1,
    const uint32_t* __restrict__ pB2,
    const float* __restrict__ bi0, const float* __restrict__ bi1,
    const float* __restrict__ bi2,
    void* __restrict__ o0, void* __restrict__ o1, void* __restrict__ o2,
    int md0, int md1, int md2, float sc0, float sc1, float sc2) {
  extern __shared__ __align__(16) char smem[];
  const int tid = threadIdx.x;
  const int w = tid >> 5, lane = tid & 31;
  const int r = lane >> 2, c = lane & 3;
  const int wm = w >> 2, wn = w & 3;
  const int z = blockIdx.z;
  const uint32_t* pB = (z == 0) ? pB0 : ((z == 1) ? pB1 : pB2);
  const float* bias = (z == 0) ? bi0 : ((z == 1) ? bi1 : bi2);
  void* out = (z == 0) ? o0 : ((z == 1) ? o1 : o2);
  const int mode = (z == 0) ? md0 : ((z == 1) ? md1 : md2);
  const float scale = (z == 0) ? sc0 : ((z == 1) ? sc1 : sc2);

  const char* Ab = (const char*)(pA + ((size_t)blockIdx.y << 16));
  const char* Bb = (const char*)(pB + ((size_t)blockIdx.x << 16));
  const uint32_t sb = smem_u32(smem);

  float acc[4][4][4] = {};

  auto load_iter = [&](int it, int s) {
    uint32_t sa = sb + s * GSTG;
    const int it2 = it * 2;
#pragma unroll
    for (int i = 0; i < 2; i++) {
      int cid = tid + i * 256;
      int mt = cid >> 6, ktl = (cid >> 5) & 1, off = cid & 31;
      CP_ASYNC16(sa + ((mt * 2 + ktl) * 32 + off) * 16,
                 Ab + ((size_t)(mt * 64 + it2 + ktl) * 32 + off) * 16);
    }
#pragma unroll
    for (int i = 0; i < 2; i++) {
      int cid = tid + i * 256;
      int nt = cid >> 5, ktl = (cid >> 4) & 1, off = cid & 15;
      CP_ASYNC16(sa + 8192 + ((nt * 2 + ktl) * 16 + off) * 16,
                 Bb + ((size_t)(nt * 64 + it2 + ktl) * 16 + off) * 16);
    }
    CP_COMMIT();
  };

  load_iter(0, 0);
  load_iter(1, 1);
  load_iter(2, 2);

  for (int it = 0; it < 32; it++) {
    CP_WAIT(2);
    __syncthreads();
    const int nx = it + 3;
    if (nx < 32) load_iter(nx, nx & 3); else CP_COMMIT();
    const char* st = smem + (it & 3) * GSTG;
#pragma unroll
    for (int ktl = 0; ktl < 2; ktl++) {
      uint2 bfr[4];
#pragma unroll
      for (int n = 0; n < 4; n++)
        bfr[n] = *(const uint2*)(st + 8192 +
                                 (((wn * 4 + n) * 2 + ktl) * 32 + lane) * 8);
      uint4 afr[4];
#pragma unroll
      for (int m = 0; m < 4; m++)
        afr[m] = *(const uint4*)(st +
                                 (((wm * 4 + m) * 2 + ktl) * 32 + lane) * 16);
#pragma unroll
      for (int n = 0; n < 4; n++)
#pragma unroll
        for (int m = 0; m < 4; m++)
          mma16(acc[m][n], (const unsigned*)&afr[m], bfr[n].x, bfr[n].y);
    }
  }

  if (mode == 3) {
    // V^T: stage fp16 [dh_local][t_local] tile in smem (272B rows), then
    // coalesced 16B stores along t.  Tile = 128 dh x 128 t.
    CP_WAIT(0);
    __syncthreads();
#pragma unroll
    for (int m = 0; m < 4; m++) {
#pragma unroll
      for (int n = 0; n < 4; n++) {
        const int coll = (wn * 4 + n) * 8 + 2 * c;
        const int colg = blockIdx.x * 128 + coll;
        const float b0 = bias[colg], b1 = bias[colg + 1];
#pragma unroll
        for (int hf = 0; hf < 2; hf++) {
          const int rowl = (wm * 4 + m) * 16 + r + 8 * hf;
          __half h0 = __float2half_rn(acc[m][n][2 * hf] + b0);
          __half h1 = __float2half_rn(acc[m][n][2 * hf + 1] + b1);
          *(__half*)(smem + coll * 272 + rowl * 2) = h0;
          *(__half*)(smem + (coll + 1) * 272 + rowl * 2) = h1;
        }
      }
    }
    __syncthreads();
    uint16_t* vt = (uint16_t*)out;
    const int b_ = (blockIdx.y * 128) >> 11;
    const int t0g = (blockIdx.y * 128) & (TT - 1);
    // 128 dh-rows x 16 segs x 16B = full 128-t coverage (2048 ids)
#pragma unroll
    for (int i = 0; i < 8; i++) {
      int id = tid + i * 256;             // 0..2047
      int dhl = id >> 4, seg = id & 15;   // 128 dh-rows x 16 x 16B
      int colg = blockIdx.x * 128 + dhl;
      int h = colg >> 6, dh = colg & (DH - 1);
      uint4 v = *(const uint4*)(smem + dhl * 272 + seg * 16);
      *(uint4*)(vt + ((size_t)(b_ * NH + h) * DH + dh) * TT + t0g + seg * 8) = v;
    }
    return;
  }

  // epilogue (modes 0, 2)
#pragma unroll
  for (int m = 0; m < 4; m++) {
    const int row0 = blockIdx.y * 128 + (wm * 4 + m) * 16 + r;
#pragma unroll
    for (int n = 0; n < 4; n++) {
      const int col = blockIdx.x * 128 + (wn * 4 + n) * 8 + 2 * c;
      const float b0 = bias[col], b1 = bias[col + 1];
#pragma unroll
      for (int hf = 0; hf < 2; hf++) {
        const int row = row0 + 8 * hf;
        float v0 = acc[m][n][2 * hf] + b0;
        float v1 = acc[m][n][2 * hf + 1] + b1;
        if (mode == 0) {
          *(float2*)((float*)out + (size_t)row * DM + col) =
              make_float2(v0, v1);
        } else {  // mode 2: rotate_half + scale, fp16 [B,H,T,Dh]
          int b_ = row >> 11, t = row & (TT - 1);
          int h = col >> 6, dh = col & (DH - 1);
          float q0 = -v1 * scale, q1 = v0 * scale;
          ((uint32_t*)out)[((size_t)(b_ * NH + h) * TT + t) * 32 + (dh >> 1)] =
              h2u(q0, q1);
        }
      }
    }
  }
}

// ---------------------------------------------------------------------------
// Flash attention v6 — proven-best R13 version (no masked-tile skip; the
// skip measured -8us in R15: no critical-path saving past __syncthreads,
// and the data-dependent branch de-optimizes the unrolled mainloop).
// fp16 mma, register-resident P, 128-key double-buffered stages.
// ---------------------------------------------------------------------------
#define HSTG 18432
#define STG128 36864
#define ATTN_SMEM (2 * STG128)   // 73728

__global__ void __launch_bounds__(256, 2) attn6(
    const uint32_t* __restrict__ Qw, const uint32_t* __restrict__ Kw,
    const uint16_t* __restrict__ Vt, uint32_t* __restrict__ pOut) {
  extern __shared__ __align__(16) char sm[];
  const uint32_t sb = smem_u32(sm);
  const int tid = threadIdx.x, w = tid >> 5, lane = tid & 31;
  const int r = lane >> 2, c = lane & 3;
  const int qb = gridDim.x - 1 - blockIdx.x;  // longest first
  const int bh = blockIdx.y;

  auto fill = [&](int jt128, int s) {
    const uint32_t base = sb + s * STG128;
    const uint32_t* Kg = Kw + ((size_t)(bh * TT + jt128 * 128)) * 32;
    const uint16_t* Vg = Vt + (size_t)bh * DH * TT + jt128 * 128;
#pragma unroll
    for (int i = 0; i < 4; i++) {
      int id = tid + i * 256;
      int row = id >> 3, sc = id & 7;
      int half = row >> 6, rl = row & 63;
      CP_ASYNC16(base + half * HSTG + rl * 144 + sc * 16,
                 Kg + row * 32 + sc * 4);
    }
#pragma unroll
    for (int i = 0; i < 4; i++) {
      int id = tid + i * 256;
      int sc = id & 7;
      int dh = (id >> 3) & 63, half = id >> 9;
      CP_ASYNC16(base + half * HSTG + 9216 + dh * 144 + sc * 16,
                 Vg + (size_t)dh * TT + half * 64 + sc * 8);
    }
    CP_COMMIT();
  };

  const uint32_t* Qu = Qw + ((size_t)bh * TT + qb * 128 + 16 * w) * 32;
  unsigned qa[4][4];
#pragma unroll
  for (int kc = 0; kc < 4; kc++) {
    qa[kc][0] = Qu[r * 32 + 8 * kc + c];
    qa[kc][1] = Qu[(r + 8) * 32 + 8 * kc + c];
    qa[kc][2] = Qu[r * 32 + 8 * kc + c + 4];
    qa[kc][3] = Qu[(r + 8) * 32 + 8 * kc + c + 4];
  }

  float o[8][4] = {};
  float mrow[2] = {-1e30f, -1e30f}, lrow[2] = {0.f, 0.f};

  const int nkt = qb + 1;   // 128-key iterations
  fill(0, 0);

  for (int jt128 = 0; jt128 < nkt; jt128++) {
    const int s = jt128 & 1;
    __syncthreads();
    if (jt128 + 1 < nkt) {
      fill(jt128 + 1, s ^ 1);
      CP_WAIT(1);
    } else {
      CP_WAIT(0);
    }
    __syncthreads();

#pragma unroll
    for (int half = 0; half < 2; half++) {
      const int jt = 2 * jt128 + half;
      const char* kbuf = sm + s * STG128 + half * HSTG;
      const char* vbuf = kbuf + 9216;

      // S = Q @ K^T (log2 domain)
      float sacc[8][4] = {};
#pragma unroll
      for (int kc = 0; kc < 4; kc++) {
#pragma unroll
        for (int ni = 0; ni < 8; ni++) {
          const uint32_t* bp =
              (const uint32_t*)(kbuf + (8 * ni + r) * 144 + (8 * kc + c) * 4);
          mma16(sacc[ni], qa[kc], bp[0], bp[4]);
        }
      }

      if (jt >= 2 * qb) {  // diagonal tiles: causal mask
        const int qrow0 = qb * 128 + 16 * w + r;
#pragma unroll
        for (int ni = 0; ni < 8; ni++) {
          const int key0 = jt * 64 + 8 * ni + 2 * c;
#pragma unroll
          for (int reg = 0; reg < 4; reg++) {
            int key = key0 + (reg & 1);
            int qr = qrow0 + 8 * (reg >> 1);
            if (key > qr) sacc[ni][reg] = -1e30f;
          }
        }
      }

      // online softmax (base-2)
#pragma unroll
      for (int h = 0; h < 2; h++) {
        float mx = -1e30f;
#pragma unroll
        for (int ni = 0; ni < 8; ni++)
          mx = fmaxf(mx, fmaxf(sacc[ni][2 * h], sacc[ni][2 * h + 1]));
        mx = fmaxf(mx, __shfl_xor_sync(0xffffffffu, mx, 1));
        mx = fmaxf(mx, __shfl_xor_sync(0xffffffffu, mx, 2));
        float mnew = fmaxf(mrow[h], mx);
        float corr = exp2f(mrow[h] - mnew);
        mrow[h] = mnew;
        float rs = 0.f;
#pragma unroll
        for (int ni = 0; ni < 8; ni++) {
          sacc[ni][2 * h] = exp2f(sacc[ni][2 * h] - mnew);
          sacc[ni][2 * h + 1] = exp2f(sacc[ni][2 * h + 1] - mnew);
          rs += sacc[ni][2 * h] + sacc[ni][2 * h + 1];
        }
        rs += __shfl_xor_sync(0xffffffffu, rs, 1);
        rs += __shfl_xor_sync(0xffffffffu, rs, 2);
        lrow[h] = lrow[h] * corr + rs;
#pragma unroll
        for (int ni = 0; ni < 8; ni++) {
          o[ni][2 * h] *= corr;
          o[ni][2 * h + 1] *= corr;
        }
      }

      // O += P @ V (QK C-frag == PV A-frag; register-resident P)
#pragma unroll
      for (int kc = 0; kc < 4; kc++) {
        unsigned pa[4];
        pa[0] = h2u(sacc[2 * kc][0], sacc[2 * kc][1]);
        pa[1] = h2u(sacc[2 * kc][2], sacc[2 * kc][3]);
        pa[2] = h2u(sacc[2 * kc + 1][0], sacc[2 * kc + 1][1]);
        pa[3] = h2u(sacc[2 * kc + 1][2], sacc[2 * kc + 1][3]);
#pragma unroll
        for (int ni = 0; ni < 8; ni++) {
          const uint32_t* vp =
              (const uint32_t*)(vbuf + (8 * ni + r) * 144 + (8 * kc + c) * 4);
          mma16(o[ni], pa, vp[0], vp[4]);
        }
      }
    }
  }

  // epilogue: normalize, fp16 packed-A fragments, uint4 stores (proven R11)
  const int b_ = bh >> 4, hh = bh & (NH - 1);
  const int mtile = b_ * 128 + qb * 8 + w;
  const float inv0 = 1.0f / lrow[0], inv1 = 1.0f / lrow[1];
#pragma unroll
  for (int k2 = 0; k2 < 4; k2++) {
    const int kt = hh * 4 + k2;
    uint4 ov = make_uint4(
        h2u(o[2 * k2][0] * inv0, o[2 * k2][1] * inv0),
        h2u(o[2 * k2][2] * inv1, o[2 * k2][3] * inv1),
        h2u(o[2 * k2 + 1][0] * inv0, o[2 * k2 + 1][1] * inv0),
        h2u(o[2 * k2 + 1][2] * inv1, o[2 * k2 + 1][3] * inv1));
    *(uint4*)(pOut + (size_t)((mtile * 64 + kt) * 32 + lane) * 4) = ov;
  }
}

extern "C" void kernel_launch(void* const* d_in, const int* in_sizes, int n_in,
                              void* d_out, int out_size) {
  const float* x  = (const float*)d_in[0];
  const float* Wq = (const float*)d_in[1];
  const float* bq = (const float*)d_in[2];
  const float* Wk = (const float*)d_in[3];
  const float* bk = (const float*)d_in[4];
  const float* Wv = (const float*)d_in[5];
  const float* bv = (const float*)d_in[6];
  const float* Wo = (const float*)d_in[7];
  const float* bo = (const float*)d_in[8];
  float* out = (float*)d_out;

  uint32_t *qp, *kp, *ap, *xp, *wp;
  uint16_t *vtp;
  cudaGetSymbolAddress((void**)&qp, g_q);
  cudaGetSymbolAddress((void**)&kp, g_k);
  cudaGetSymbolAddress((void**)&vtp, g_vt);
  cudaGetSymbolAddress((void**)&ap, g_attp);
  cudaGetSymbolAddress((void**)&xp, g_xp);
  cudaGetSymbolAddress((void**)&wp, g_wp);

  static int attr_set = 0;
  if (!attr_set) {
    cudaFuncSetAttribute(gemm_fp16, cudaFuncAttributeMaxDynamicSharedMemorySize,
                         GEMM_SMEM);
    cudaFuncSetAttribute(attn6, cudaFuncAttributeMaxDynamicSharedMemorySize,
                         ATTN_SMEM);
    attr_set = 1;
  }

  const float QSCALE = 0.125f * 1.4426950408889634f;  // 1/sqrt(Dh) * log2(e)
  const size_t WSZ = (size_t)DM * DM / 2;             // words per packed W

  // 1) pack inputs into fp16 fragment layouts (coalesced)
  pack_all<<<dim3(512, 1, 5), 256>>>(x, Wq, Wk, Wv, Wo, xp, wp);

  // 2) fused QKV: Q,K -> fp16 rot (+Q scale); V -> fp16 transposed (staged)
  gemm_fp16<<<dim3(8, 32, 3), 256, GEMM_SMEM>>>(
      xp, wp, wp + WSZ, wp + 2 * WSZ, bq, bk, bv, qp, kp, vtp,
      2, 2, 3, QSCALE, 1.f, 1.f);

  // 3) attention (128-key stages, register-resident P)
  attn6<<<dim3(16, 32), 256, ATTN_SMEM>>>(qp, kp, vtp, ap);

  // 4) output projection (fp32 out)
  gemm_fp16<<<dim3(8, 32, 1), 256, GEMM_SMEM>>>(
      ap, wp + 3 * WSZ, wp + 3 * WSZ, wp + 3 * WSZ, bo, bo, bo, out, out, out,
      0, 0, 0, 1.f, 1.f, 1.f);
}

// round 17
// speedup vs baseline: 1.0475x; 1.0036x over previous
#include <cuda_runtime.h>
#include <cuda_fp16.h>
#include <cstdint>

#define BB 2
#define TT 2048
#define DM 1024
#define NH 16
#define DH 64
#define MM (BB * TT)   // 4096

// Scratch (device globals; no allocation allowed)
__device__ uint32_t g_q[BB * NH * TT * (DH / 2)];   // fp16 [B,H,T,Dh], *0.125*log2e
__device__ uint32_t g_k[BB * NH * TT * (DH / 2)];   // fp16 [B,H,T,Dh]
__device__ uint16_t g_vt[BB * NH * DH * TT];        // fp16 [B,H,Dh,T] (transposed)
__device__ uint32_t g_attp[MM * DM / 2];            // attn out, fp16 packed-A frags
__device__ uint32_t g_xp[MM * DM / 2];              // x fp16 packed-A frags
__device__ uint32_t g_wp[4 * DM * DM / 2];          // W's fp16 packed-B frags

// ---------------------------------------------------------------------------
// helpers
// ---------------------------------------------------------------------------
__device__ __forceinline__ uint32_t smem_u32(const void* p) {
  uint32_t a;
  asm("{ .reg .u64 t; cvta.to.shared.u64 t, %1; cvt.u32.u64 %0, t; }"
      : "=r"(a) : "l"(p));
  return a;
}

__device__ __forceinline__ uint32_t h2u(float lo, float hi) {
  __half2 h = __floats2half2_rn(lo, hi);
  return *reinterpret_cast<uint32_t*>(&h);
}

// fp16 m16n8k16
__device__ __forceinline__ void mma16(float* c, const unsigned* a,
                                      unsigned b0, unsigned b1) {
  asm("mma.sync.aligned.m16n8k16.row.col.f32.f16.f16.f32 "
      "{%0,%1,%2,%3},{%4,%5,%6,%7},{%8,%9},{%0,%1,%2,%3};"
      : "+f"(c[0]), "+f"(c[1]), "+f"(c[2]), "+f"(c[3])
      : "r"(a[0]), "r"(a[1]), "r"(a[2]), "r"(a[3]), "r"(b0), "r"(b1));
}

#define CP_ASYNC16(dst, src) \
  asm volatile("cp.async.cg.shared.global [%0], [%1], 16;" :: "r"(dst), "l"(src))
#define CP_COMMIT() asm volatile("cp.async.commit_group;" ::: "memory")
#define CP_WAIT(n)  asm volatile("cp.async.wait_group %0;" :: "n"(n) : "memory")

// ---------------------------------------------------------------------------
// Packing into fp16 mma fragment order — coalesced (proven R11).
// ---------------------------------------------------------------------------
__global__ void pack_all(const float* __restrict__ x,
                         const float* __restrict__ Wq,
                         const float* __restrict__ Wk,
                         const float* __restrict__ Wv,
                         const float* __restrict__ Wo,
                         uint32_t* __restrict__ pX,
                         uint32_t* __restrict__ pW) {
  const int z = blockIdx.z;
  const int idx0 = blockIdx.x * blockDim.x + threadIdx.x;
  const int stride = gridDim.x * blockDim.x;
  if (z == 0) {
    for (int i = idx0; i < (MM / 16) * 64 * 32; i += stride) {
      int lane = i & 31, kt = (i >> 5) & 63, mt = i >> 11;
      int g7 = lane >> 2, t0 = lane & 3;
      const float* r0 = x + (size_t)(mt * 16 + g7) * DM + kt * 16 + 2 * t0;
      const float* r1 = r0 + 8 * DM;
      float2 a0 = *(const float2*)(r0);
      float2 a1 = *(const float2*)(r1);
      float2 a2 = *(const float2*)(r0 + 8);
      float2 a3 = *(const float2*)(r1 + 8);
      uint4 o = make_uint4(h2u(a0.x, a0.y), h2u(a1.x, a1.y),
                           h2u(a2.x, a2.y), h2u(a3.x, a3.y));
      *(uint4*)(pX + (size_t)((mt * 64 + kt) * 32 + lane) * 4) = o;
    }
  } else {
    const float* W = (z == 1) ? Wq : ((z == 2) ? Wk : ((z == 3) ? Wv : Wo));
    uint32_t* dst = pW + (size_t)(z - 1) * (DM * DM / 2);
    for (int i = idx0; i < (DM / 8) * 64 * 32; i += stride) {
      int lane = i & 31, kt = (i >> 5) & 63, nt = i >> 11;
      int g = lane >> 2, t0 = lane & 3;
      const float* rw = W + (size_t)(nt * 8 + g) * DM + kt * 16 + 2 * t0;
      float2 b0 = *(const float2*)(rw);
      float2 b1 = *(const float2*)(rw + 8);
      uint2 o = make_uint2(h2u(b0.x, b0.y), h2u(b1.x, b1.y));
      *(uint2*)(dst + (size_t)((nt * 64 + kt) * 64 + lane * 2)) = o;
    }
  }
}

// ---------------------------------------------------------------------------
// GEMM (fp16 m16n8k16) — proven-best R13 config (29.6us O-proj).
// Block 128x128, 8 warps (2m x 4n), warp tile 64x32, k-step 32,
// 4-stage cp.async (16KB/stage), 2 CTAs/SM.
// modes: 0 plain fp32 [M,DM]; 2 head-split+rotate -> fp16 [B,H,T,Dh] (*scale);
//        3 head-split -> fp16 transposed [B,H,Dh,T] via smem-staged stores.
// ---------------------------------------------------------------------------
#define GSTG 16384
#define GEMM_SMEM (4 * GSTG)   // 65536

__global__ void __launch_bounds__(256, 2) gemm_fp16(
    const uint32_t* __restrict__ pA,
    const uint32_t* __restrict__ pB0, const uint32_t* __restrict__ pB1,
    const uint32_t* __restrict__ pB2,
    const float* __restrict__ bi0, const float* __restrict__ bi1,
    const float* __restrict__ bi2,
    void* __restrict__ o0, void* __restrict__ o1, void* __restrict__ o2,
    int md0, int md1, int md2, float sc0, float sc1, float sc2) {
  extern __shared__ __align__(16) char smem[];
  const int tid = threadIdx.x;
  const int w = tid >> 5, lane = tid & 31;
  const int r = lane >> 2, c = lane & 3;
  const int wm = w >> 2, wn = w & 3;
  const int z = blockIdx.z;
  const uint32_t* pB = (z == 0) ? pB0 : ((z == 1) ? pB1 : pB2);
  const float* bias = (z == 0) ? bi0 : ((z == 1) ? bi1 : bi2);
  void* out = (z == 0) ? o0 : ((z == 1) ? o1 : o2);
  const int mode = (z == 0) ? md0 : ((z == 1) ? md1 : md2);
  const float scale = (z == 0) ? sc0 : ((z == 1) ? sc1 : sc2);

  const char* Ab = (const char*)(pA + ((size_t)blockIdx.y << 16));
  const char* Bb = (const char*)(pB + ((size_t)blockIdx.x << 16));
  const uint32_t sb = smem_u32(smem);

  float acc[4][4][4] = {};

  auto load_iter = [&](int it, int s) {
    uint32_t sa = sb + s * GSTG;
    const int it2 = it * 2;
#pragma unroll
    for (int i = 0; i < 2; i++) {
      int cid = tid + i * 256;
      int mt = cid >> 6, ktl = (cid >> 5) & 1, off = cid & 31;
      CP_ASYNC16(sa + ((mt * 2 + ktl) * 32 + off) * 16,
                 Ab + ((size_t)(mt * 64 + it2 + ktl) * 32 + off) * 16);
    }
#pragma unroll
    for (int i = 0; i < 2; i++) {
      int cid = tid + i * 256;
      int nt = cid >> 5, ktl = (cid >> 4) & 1, off = cid & 15;
      CP_ASYNC16(sa + 8192 + ((nt * 2 + ktl) * 16 + off) * 16,
                 Bb + ((size_t)(nt * 64 + it2 + ktl) * 16 + off) * 16);
    }
    CP_COMMIT();
  };

  load_iter(0, 0);
  load_iter(1, 1);
  load_iter(2, 2);

  for (int it = 0; it < 32; it++) {
    CP_WAIT(2);
    __syncthreads();
    const int nx = it + 3;
    if (nx < 32) load_iter(nx, nx & 3); else CP_COMMIT();
    const char* st = smem + (it & 3) * GSTG;
#pragma unroll
    for (int ktl = 0; ktl < 2; ktl++) {
      uint2 bfr[4];
#pragma unroll
      for (int n = 0; n < 4; n++)
        bfr[n] = *(const uint2*)(st + 8192 +
                                 (((wn * 4 + n) * 2 + ktl) * 32 + lane) * 8);
      uint4 afr[4];
#pragma unroll
      for (int m = 0; m < 4; m++)
        afr[m] = *(const uint4*)(st +
                                 (((wm * 4 + m) * 2 + ktl) * 32 + lane) * 16);
#pragma unroll
      for (int n = 0; n < 4; n++)
#pragma unroll
        for (int m = 0; m < 4; m++)
          mma16(acc[m][n], (const unsigned*)&afr[m], bfr[n].x, bfr[n].y);
    }
  }

  if (mode == 3) {
    // V^T: stage fp16 [dh_local][t_local] tile in smem (272B rows), then
    // coalesced 16B stores along t.  Tile = 128 dh x 128 t.
    CP_WAIT(0);
    __syncthreads();
#pragma unroll
    for (int m = 0; m < 4; m++) {
#pragma unroll
      for (int n = 0; n < 4; n++) {
        const int coll = (wn * 4 + n) * 8 + 2 * c;
        const int colg = blockIdx.x * 128 + coll;
        const float b0 = bias[colg], b1 = bias[colg + 1];
#pragma unroll
        for (int hf = 0; hf < 2; hf++) {
          const int rowl = (wm * 4 + m) * 16 + r + 8 * hf;
          __half h0 = __float2half_rn(acc[m][n][2 * hf] + b0);
          __half h1 = __float2half_rn(acc[m][n][2 * hf + 1] + b1);
          *(__half*)(smem + coll * 272 + rowl * 2) = h0;
          *(__half*)(smem + (coll + 1) * 272 + rowl * 2) = h1;
        }
      }
    }
    __syncthreads();
    uint16_t* vt = (uint16_t*)out;
    const int b_ = (blockIdx.y * 128) >> 11;
    const int t0g = (blockIdx.y * 128) & (TT - 1);
    // 128 dh-rows x 16 segs x 16B = full 128-t coverage (2048 ids)
#pragma unroll
    for (int i = 0; i < 8; i++) {
      int id = tid + i * 256;             // 0..2047
      int dhl = id >> 4, seg = id & 15;   // 128 dh-rows x 16 x 16B
      int colg = blockIdx.x * 128 + dhl;
      int h = colg >> 6, dh = colg & (DH - 1);
      uint4 v = *(const uint4*)(smem + dhl * 272 + seg * 16);
      *(uint4*)(vt + ((size_t)(b_ * NH + h) * DH + dh) * TT + t0g + seg * 8) = v;
    }
    return;
  }

  // epilogue (modes 0, 2)
#pragma unroll
  for (int m = 0; m < 4; m++) {
    const int row0 = blockIdx.y * 128 + (wm * 4 + m) * 16 + r;
#pragma unroll
    for (int n = 0; n < 4; n++) {
      const int col = blockIdx.x * 128 + (wn * 4 + n) * 8 + 2 * c;
      const float b0 = bias[col], b1 = bias[col + 1];
#pragma unroll
      for (int hf = 0; hf < 2; hf++) {
        const int row = row0 + 8 * hf;
        float v0 = acc[m][n][2 * hf] + b0;
        float v1 = acc[m][n][2 * hf + 1] + b1;
        if (mode == 0) {
          *(float2*)((float*)out + (size_t)row * DM + col) =
              make_float2(v0, v1);
        } else {  // mode 2: rotate_half + scale, fp16 [B,H,T,Dh]
          int b_ = row >> 11, t = row & (TT - 1);
          int h = col >> 6, dh = col & (DH - 1);
          float q0 = -v1 * scale, q1 = v0 * scale;
          ((uint32_t*)out)[((size_t)(b_ * NH + h) * TT + t) * 32 + (dh >> 1)] =
              h2u(q0, q1);
        }
      }
    }
  }
}

// ---------------------------------------------------------------------------
// Flash attention v6 — proven-best R13 version (no masked-tile skip; the
// skip measured -8us in R15: no critical-path saving past __syncthreads,
// and the data-dependent branch de-optimizes the unrolled mainloop).
// fp16 mma, register-resident P, 128-key double-buffered stages.
// ---------------------------------------------------------------------------
#define HSTG 18432
#define STG128 36864
#define ATTN_SMEM (2 * STG128)   // 73728

__global__ void __launch_bounds__(256, 2) attn6(
    const uint32_t* __restrict__ Qw, const uint32_t* __restrict__ Kw,
    const uint16_t* __restrict__ Vt, uint32_t* __restrict__ pOut) {
  extern __shared__ __align__(16) char sm[];
  const uint32_t sb = smem_u32(sm);
  const int tid = threadIdx.x, w = tid >> 5, lane = tid & 31;
  const int r = lane >> 2, c = lane & 3;
  const int qb = gridDim.x - 1 - blockIdx.x;  // longest first
  const int bh = blockIdx.y;

  auto fill = [&](int jt128, int s) {
    const uint32_t base = sb + s * STG128;
    const uint32_t* Kg = Kw + ((size_t)(bh * TT + jt128 * 128)) * 32;
    const uint16_t* Vg = Vt + (size_t)bh * DH * TT + jt128 * 128;
#pragma unroll
    for (int i = 0; i < 4; i++) {
      int id = tid + i * 256;
      int row = id >> 3, sc = id & 7;
      int half = row >> 6, rl = row & 63;
      CP_ASYNC16(base + half * HSTG + rl * 144 + sc * 16,
                 Kg + row * 32 + sc * 4);
    }
#pragma unroll
    for (int i = 0; i < 4; i++) {
      int id = tid + i * 256;
      int sc = id & 7;
      int dh = (id >> 3) & 63, half = id >> 9;
      CP_ASYNC16(base + half * HSTG + 9216 + dh * 144 + sc * 16,
                 Vg + (size_t)dh * TT + half * 64 + sc * 8);
    }
    CP_COMMIT();
  };

  const uint32_t* Qu = Qw + ((size_t)bh * TT + qb * 128 + 16 * w) * 32;
  unsigned qa[4][4];
#pragma unroll
  for (int kc = 0; kc < 4; kc++) {
    qa[kc][0] = Qu[r * 32 + 8 * kc + c];
    qa[kc][1] = Qu[(r + 8) * 32 + 8 * kc + c];
    qa[kc][2] = Qu[r * 32 + 8 * kc + c + 4];
    qa[kc][3] = Qu[(r + 8) * 32 + 8 * kc + c + 4];
  }

  float o[8][4] = {};
  float mrow[2] = {-1e30f, -1e30f}, lrow[2] = {0.f, 0.f};

  const int nkt = qb + 1;   // 128-key iterations
  fill(0, 0);

  for (int jt128 = 0; jt128 < nkt; jt128++) {
    const int s = jt128 & 1;
    __syncthreads();
    if (jt128 + 1 < nkt) {
      fill(jt128 + 1, s ^ 1);
      CP_WAIT(1);
    } else {
      CP_WAIT(0);
    }
    __syncthreads();

#pragma unroll
    for (int half = 0; half < 2; half++) {
      const int jt = 2 * jt128 + half;
      const char* kbuf = sm + s * STG128 + half * HSTG;
      const char* vbuf = kbuf + 9216;

      // S = Q @ K^T (log2 domain)
      float sacc[8][4] = {};
#pragma unroll
      for (int kc = 0; kc < 4; kc++) {
#pragma unroll
        for (int ni = 0; ni < 8; ni++) {
          const uint32_t* bp =
              (const uint32_t*)(kbuf + (8 * ni + r) * 144 + (8 * kc + c) * 4);
          mma16(sacc[ni], qa[kc], bp[0], bp[4]);
        }
      }

      if (jt >= 2 * qb) {  // diagonal tiles: causal mask
        const int qrow0 = qb * 128 + 16 * w + r;
#pragma unroll
        for (int ni = 0; ni < 8; ni++) {
          const int key0 = jt * 64 + 8 * ni + 2 * c;
#pragma unroll
          for (int reg = 0; reg < 4; reg++) {
            int key = key0 + (reg & 1);
            int qr = qrow0 + 8 * (reg >> 1);
            if (key > qr) sacc[ni][reg] = -1e30f;
          }
        }
      }

      // online softmax (base-2)
#pragma unroll
      for (int h = 0; h < 2; h++) {
        float mx = -1e30f;
#pragma unroll
        for (int ni = 0; ni < 8; ni++)
          mx = fmaxf(mx, fmaxf(sacc[ni][2 * h], sacc[ni][2 * h + 1]));
        mx = fmaxf(mx, __shfl_xor_sync(0xffffffffu, mx, 1));
        mx = fmaxf(mx, __shfl_xor_sync(0xffffffffu, mx, 2));
        float mnew = fmaxf(mrow[h], mx);
        float corr = exp2f(mrow[h] - mnew);
        mrow[h] = mnew;
        float rs = 0.f;
#pragma unroll
        for (int ni = 0; ni < 8; ni++) {
          sacc[ni][2 * h] = exp2f(sacc[ni][2 * h] - mnew);
          sacc[ni][2 * h + 1] = exp2f(sacc[ni][2 * h + 1] - mnew);
          rs += sacc[ni][2 * h] + sacc[ni][2 * h + 1];
        }
        rs += __shfl_xor_sync(0xffffffffu, rs, 1);
        rs += __shfl_xor_sync(0xffffffffu, rs, 2);
        lrow[h] = lrow[h] * corr + rs;
#pragma unroll
        for (int ni = 0; ni < 8; ni++) {
          o[ni][2 * h] *= corr;
          o[ni][2 * h + 1] *= corr;
        }
      }

      // O += P @ V (QK C-frag == PV A-frag; register-resident P)
#pragma unroll
      for (int kc = 0; kc < 4; kc++) {
        unsigned pa[4];
        pa[0] = h2u(sacc[2 * kc][0], sacc[2 * kc][1]);
        pa[1] = h2u(sacc[2 * kc][2], sacc[2 * kc][3]);
        pa[2] = h2u(sacc[2 * kc + 1][0], sacc[2 * kc + 1][1]);
        pa[3] = h2u(sacc[2 * kc + 1][2], sacc[2 * kc + 1][3]);
#pragma unroll
        for (int ni = 0; ni < 8; ni++) {
          const uint32_t* vp =
              (const uint32_t*)(vbuf + (8 * ni + r) * 144 + (8 * kc + c) * 4);
          mma16(o[ni], pa, vp[0], vp[4]);
        }
      }
    }
  }

  // epilogue: normalize, fp16 packed-A fragments, uint4 stores (proven R11)
  const int b_ = bh >> 4, hh = bh & (NH - 1);
  const int mtile = b_ * 128 + qb * 8 + w;
  const float inv0 = 1.0f / lrow[0], inv1 = 1.0f / lrow[1];
#pragma unroll
  for (int k2 = 0; k2 < 4; k2++) {
    const int kt = hh * 4 + k2;
    uint4 ov = make_uint4(
        h2u(o[2 * k2][0] * inv0, o[2 * k2][1] * inv0),
        h2u(o[2 * k2][2] * inv1, o[2 * k2][3] * inv1),
        h2u(o[2 * k2 + 1][0] * inv0, o[2 * k2 + 1][1] * inv0),
        h2u(o[2 * k2 + 1][2] * inv1, o[2 * k2 + 1][3] * inv1));
    *(uint4*)(pOut + (size_t)((mtile * 64 + kt) * 32 + lane) * 4) = ov;
  }
}

extern "C" void kernel_launch(void* const* d_in, const int* in_sizes, int n_in,
                              void* d_out, int out_size) {
  const float* x  = (const float*)d_in[0];
  const float* Wq = (const float*)d_in[1];
  const float* bq = (const float*)d_in[2];
  const float* Wk = (const float*)d_in[3];
  const float* bk = (const float*)d_in[4];
  const float* Wv = (const float*)d_in[5];
  const float* bv = (const float*)d_in[6];
  const float* Wo = (const float*)d_in[7];
  const float* bo = (const float*)d_in[8];
  float* out = (float*)d_out;

  uint32_t *qp, *kp, *ap, *xp, *wp;
  uint16_t *vtp;
  cudaGetSymbolAddress((void**)&qp, g_q);
  cudaGetSymbolAddress((void**)&kp, g_k);
  cudaGetSymbolAddress((void**)&vtp, g_vt);
  cudaGetSymbolAddress((void**)&ap, g_attp);
  cudaGetSymbolAddress((void**)&xp, g_xp);
  cudaGetSymbolAddress((void**)&wp, g_wp);

  static int attr_set = 0;
  if (!attr_set) {
    cudaFuncSetAttribute(gemm_fp16, cudaFuncAttributeMaxDynamicSharedMemorySize,
                         GEMM_SMEM);
    cudaFuncSetAttribute(attn6, cudaFuncAttributeMaxDynamicSharedMemorySize,
                         ATTN_SMEM);
    attr_set = 1;
  }

  const float QSCALE = 0.125f * 1.4426950408889634f;  // 1/sqrt(Dh) * log2(e)
  const size_t WSZ = (size_t)DM * DM / 2;             // words per packed W

  // 1) pack inputs into fp16 fragment layouts (coalesced)
  pack_all<<<dim3(512, 1, 5), 256>>>(x, Wq, Wk, Wv, Wo, xp, wp);

  // 2) fused QKV: Q,K -> fp16 rot (+Q scale); V -> fp16 transposed (staged)
  gemm_fp16<<<dim3(8, 32, 3), 256, GEMM_SMEM>>>(
      xp, wp, wp + WSZ, wp + 2 * WSZ, bq, bk, bv, qp, kp, vtp,
      2, 2, 3, QSCALE, 1.f, 1.f);

  // 3) attention (128-key stages, register-resident P)
  attn6<<<dim3(16, 32), 256, ATTN_SMEM>>>(qp, kp, vtp, ap);

  // 4) output projection (fp32 out)
  gemm_fp16<<<dim3(8, 32, 1), 256, GEMM_SMEM>>>(
      ap, wp + 3 * WSZ, wp + 3 * WSZ, wp + 3 * WSZ, bo, bo, bo, out, out, out,
      0, 0, 0, 1.f, 1.f, 1.f);
}